// round 1
// baseline (speedup 1.0000x reference)
#include <cuda_runtime.h>
#include <math.h>

#define NHEADS 8
#define HC     32
#define HDIM   64
#define WDIM   64
#define HW     4096
#define CDIM   256
#define BDIM   8
#define LDIM   80

// ---------- scratch (device globals: allowed; no allocation APIs) ----------
__device__ float g_wT[CDIM * 9 * CDIM];          // [(ci*9+tap)*256 + co], BN-folded
__device__ float g_beta2[CDIM];                  // beta - mean*inv
__device__ float g_attn[BDIM * NHEADS * HW];     // sigmoid gate per (b, head, pixel)

// ---------- K0: fold BN into conv weights, transpose for coalesced loads ----------
__global__ void prep_kernel(const float* __restrict__ conv_w,
                            const float* __restrict__ gamma,
                            const float* __restrict__ beta,
                            const float* __restrict__ mean,
                            const float* __restrict__ var) {
    int idx = blockIdx.x * 256 + threadIdx.x;    // over [co][ci][tap], co-major (coalesced read)
    if (idx < CDIM * CDIM * 9) {
        int co  = idx / (CDIM * 9);
        int r   = idx % (CDIM * 9);
        int ci  = r / 9;
        int tap = r % 9;
        float inv = gamma[co] * rsqrtf(var[co] + 1e-3f);
        g_wT[(ci * 9 + tap) * CDIM + co] = conv_w[idx] * inv;
    }
    if (idx < CDIM) {
        float inv = gamma[idx] * rsqrtf(var[idx] + 1e-3f);
        g_beta2[idx] = beta[idx] - mean[idx] * inv;
    }
}

// ---------- K1: fused 1x1 proj + text attention + max + sigmoid*scale ----------
// grid: (16 pixel-tiles, 8 heads, 8 batch), block: 256 threads (1 pixel each)
__global__ void __launch_bounds__(256) attn_kernel(
    const float* __restrict__ img,
    const float* __restrict__ text,
    const float* __restrict__ proj_w,
    const float* __restrict__ proj_b,
    const float* __restrict__ attn_bias,
    const float* __restrict__ scale) {

    __shared__ __align__(16) float W_s[HC * CDIM];   // [cc][cin]
    __shared__ __align__(16) float T_s[LDIM * HC];   // [n][cc]

    const int tid  = threadIdx.x;
    const int tile = blockIdx.x;
    const int head = blockIdx.y;
    const int b    = blockIdx.z;

    // load head's proj weights: W_s[cc][cin] = proj_w[(head*32+cc)*256 + cin] (coalesced)
    for (int i = tid; i < HC * CDIM; i += 256) {
        W_s[i] = proj_w[head * HC * CDIM + i];
    }
    // load text slice: T_s[n][cc] = text[b, n, head*32+cc] (coalesced per token)
    for (int i = tid; i < LDIM * HC; i += 256) {
        int n = i >> 5, cc = i & 31;
        T_s[i] = text[(b * LDIM + n) * CDIM + head * HC + cc];
    }
    __syncthreads();

    const int pix = tile * 256 + tid;
    const float* imgp = img + ((size_t)b * CDIM) * HW + pix;

    float acc[HC];
    #pragma unroll
    for (int cc = 0; cc < HC; cc++) acc[cc] = proj_b[head * HC + cc];

    // i_feat[cc] = sum_cin W[cc][cin] * img[cin]  — process 4 cin at a time via float4 weights
    const float4* W4 = reinterpret_cast<const float4*>(W_s);
    #pragma unroll 2
    for (int cin = 0; cin < CDIM; cin += 4) {
        float v0 = imgp[(cin + 0) * HW];
        float v1 = imgp[(cin + 1) * HW];
        float v2 = imgp[(cin + 2) * HW];
        float v3 = imgp[(cin + 3) * HW];
        int q = cin >> 2;
        #pragma unroll
        for (int cc = 0; cc < HC; cc++) {
            float4 w = W4[cc * (CDIM / 4) + q];   // broadcast LDS.128
            acc[cc] += w.x * v0 + w.y * v1 + w.z * v2 + w.w * v3;
        }
    }

    // scores against 80 tokens, running max (2 tokens in flight, 2 partial sums each)
    float best = -1e30f;
    #pragma unroll 2
    for (int n = 0; n < LDIM; n += 2) {
        float s0a = 0.f, s0b = 0.f, s1a = 0.f, s1b = 0.f;
        #pragma unroll
        for (int cc = 0; cc < HC; cc += 2) {
            s0a += acc[cc]     * T_s[n * HC + cc];
            s0b += acc[cc + 1] * T_s[n * HC + cc + 1];
            s1a += acc[cc]     * T_s[(n + 1) * HC + cc];
            s1b += acc[cc + 1] * T_s[(n + 1) * HC + cc + 1];
        }
        best = fmaxf(best, fmaxf(s0a + s0b, s1a + s1b));
    }

    const float inv_sqrt_hc = 0.17677669529663687f;  // 1/sqrt(32)
    float z = best * inv_sqrt_hc + attn_bias[head];
    float a = (1.0f / (1.0f + expf(-z))) * scale[head];
    g_attn[((b * NHEADS + head) << 12) + pix] = a;
}

// ---------- K2: 3x3 conv (BN folded) + attention gate ----------
// grid: (8 row-tiles, 8 cout-blocks(=heads), 8 batch), block 256 threads
// block tile: 64(W) x 8(H) pixels x 32 couts; thread: 4px * 2py * 8co = 64 outputs
#define CI_T 8
#define RS   80        // smem row stride: 80 % 32 == 16 -> conflict-free half-warps

__global__ void __launch_bounds__(256, 2) conv_gate_kernel(
    const float* __restrict__ img, float* __restrict__ out) {

    __shared__ __align__(16) float in_s[CI_T * 10 * RS];   // 6400 f = 25.6 KB
    __shared__ __align__(16) float w_s[CI_T * 9 * 32];     // 2304 f = 9.2 KB

    const int tid = threadIdx.x;
    const int tx  = tid & 15;          // pixel-x base (x = tx + j*16)
    const int ty  = (tid >> 4) & 3;    // pixel-y base (y = ty + i*4)
    const int cg  = tid >> 6;          // cout group (co = cg*8 + k)
    const int ht  = blockIdx.x;        // row tile
    const int cob = blockIdx.y;        // cout block == head
    const int b   = blockIdx.z;

    const int hbase = ht * 8;
    const float* imgb = img + (size_t)b * CDIM * HW;

    float acc[2][4][8];
    #pragma unroll
    for (int i = 0; i < 2; i++)
        #pragma unroll
        for (int j = 0; j < 4; j++)
            #pragma unroll
            for (int k = 0; k < 8; k++) acc[i][j][k] = 0.f;

    for (int cib = 0; cib < CDIM; cib += CI_T) {
        // --- load input tile with halo (zero-pad borders) ---
        for (int idx = tid; idx < CI_T * 10 * 66; idx += 256) {
            int ci = idx / 660;
            int r  = idx % 660;
            int sy = r / 66, sx = r % 66;
            int gy = hbase + sy - 1;
            int gx = sx - 1;
            float v = 0.f;
            if ((unsigned)gy < 64u && (unsigned)gx < 64u)
                v = imgb[(cib + ci) * HW + (gy << 6) + gx];
            in_s[ci * (10 * RS) + sy * RS + sx] = v;
        }
        // --- load weight tile: w_s[(ci*9+tap)*32 + co] (coalesced from g_wT) ---
        for (int idx = tid; idx < CI_T * 9 * 32; idx += 256) {
            int ci_tap = idx >> 5;
            int co     = idx & 31;
            w_s[idx] = g_wT[(cib * 9 + ci_tap) * CDIM + cob * 32 + co];
        }
        __syncthreads();

        #pragma unroll 2
        for (int ci = 0; ci < CI_T; ci++) {
            const float* ins = &in_s[ci * (10 * RS)];
            #pragma unroll
            for (int t = 0; t < 9; t++) {
                const int ky = t / 3, kx = t % 3;
                float4 w0 = *reinterpret_cast<const float4*>(&w_s[(ci * 9 + t) * 32 + cg * 8]);
                float4 w1 = *reinterpret_cast<const float4*>(&w_s[(ci * 9 + t) * 32 + cg * 8 + 4]);
                float v[2][4];
                #pragma unroll
                for (int i = 0; i < 2; i++)
                    #pragma unroll
                    for (int j = 0; j < 4; j++)
                        v[i][j] = ins[(ty + i * 4 + ky) * RS + tx + j * 16 + kx];
                #pragma unroll
                for (int i = 0; i < 2; i++)
                    #pragma unroll
                    for (int j = 0; j < 4; j++) {
                        float vv = v[i][j];
                        acc[i][j][0] += vv * w0.x;
                        acc[i][j][1] += vv * w0.y;
                        acc[i][j][2] += vv * w0.z;
                        acc[i][j][3] += vv * w0.w;
                        acc[i][j][4] += vv * w1.x;
                        acc[i][j][5] += vv * w1.y;
                        acc[i][j][6] += vv * w1.z;
                        acc[i][j][7] += vv * w1.w;
                    }
            }
        }
        __syncthreads();
    }

    // --- epilogue: +beta2, * attn gate, store ---
    float beta2v[8];
    #pragma unroll
    for (int k = 0; k < 8; k++) beta2v[k] = g_beta2[cob * 32 + cg * 8 + k];

    const float* attnp = &g_attn[((b * NHEADS + cob) << 12)];
    #pragma unroll
    for (int i = 0; i < 2; i++) {
        #pragma unroll
        for (int j = 0; j < 4; j++) {
            int gy = hbase + ty + i * 4;
            int gx = tx + j * 16;
            float a = attnp[(gy << 6) + gx];
            #pragma unroll
            for (int k = 0; k < 8; k++) {
                int co = cob * 32 + cg * 8 + k;
                out[(((size_t)b * CDIM + co) << 12) + (gy << 6) + gx] =
                    (acc[i][j][k] + beta2v[k]) * a;
            }
        }
    }
}

// ---------- launch ----------
extern "C" void kernel_launch(void* const* d_in, const int* in_sizes, int n_in,
                              void* d_out, int out_size) {
    const float* img_feat   = (const float*)d_in[0];
    const float* text_feats = (const float*)d_in[1];
    const float* proj_w     = (const float*)d_in[2];
    const float* proj_b     = (const float*)d_in[3];
    const float* attn_bias  = (const float*)d_in[4];
    const float* scale      = (const float*)d_in[5];
    const float* conv_w     = (const float*)d_in[6];
    const float* bn_gamma   = (const float*)d_in[7];
    const float* bn_beta    = (const float*)d_in[8];
    const float* bn_mean    = (const float*)d_in[9];
    const float* bn_var     = (const float*)d_in[10];
    float* out = (float*)d_out;

    prep_kernel<<<(CDIM * CDIM * 9 + 255) / 256, 256>>>(conv_w, bn_gamma, bn_beta, bn_mean, bn_var);

    dim3 g1(HW / 256, NHEADS, BDIM);
    attn_kernel<<<g1, 256>>>(img_feat, text_feats, proj_w, proj_b, attn_bias, scale);

    dim3 g2(HDIM / 8, CDIM / 32, BDIM);
    conv_gate_kernel<<<g2, 256>>>(img_feat, out);
}